// round 7
// baseline (speedup 1.0000x reference)
#include <cuda_runtime.h>
#include <math.h>

// ---------------------------------------------------------------------------
// Problem constants (fixed by the reference)
// ---------------------------------------------------------------------------
static constexpr int Bc  = 2;
static constexpr int Sc  = 2048;
static constexpr int Ec  = 2048;
static constexpr int Hc  = 16;
static constexpr int DHc = 128;
static constexpr int Lc  = 64;
static constexpr int Mc  = Bc * Sc;      // 4096 rows

// ---------------------------------------------------------------------------
// Device scratch (static allocation is the sanctioned workaround)
// ---------------------------------------------------------------------------
__device__ float g_q   [(size_t)Mc * Ec];
__device__ float g_k   [(size_t)Mc * Ec];
__device__ float g_v   [(size_t)Mc * Ec];
__device__ float g_qlat[(size_t)Bc * Hc * Sc * Lc];
__device__ float g_klat[(size_t)Bc * Hc * Sc * Lc];
__device__ float g_att [(size_t)Mc * Ec];
__device__ float g_mix [(size_t)Mc * Ec];

// ---------------------------------------------------------------------------
// Generic GEMM + bias : C[M,N] = A[M,K] @ B[K,N] + bias[N]
// 128x128 tile, BK=16, 256 threads, 8x8 per thread.
// Double-buffered smem mainloop with register prefetch.
// ---------------------------------------------------------------------------
__global__ void __launch_bounds__(256) gemm_bias_kernel(
    const float* __restrict__ A, const float* __restrict__ Bm,
    const float* __restrict__ bias, float* __restrict__ C,
    int M, int N, int K)
{
    __shared__ float As[2][16][128];
    __shared__ float Bs[2][16][128];

    const int tid = threadIdx.x;
    const int ty  = tid >> 4;
    const int tx  = tid & 15;
    const int row0 = blockIdx.y * 128;
    const int col0 = blockIdx.x * 128;

    // per-thread load coordinates (2 float4s each for A and B per tile)
    int arr[2], acc_[2], brr[2], bcc[2];
#pragma unroll
    for (int u = 0; u < 2; u++) {
        int f = tid * 2 + u;          // 0..511
        arr[u]  = f >> 2;             // 0..127
        acc_[u] = (f & 3) << 2;       // 0..12
        brr[u]  = f >> 5;             // 0..15
        bcc[u]  = (f & 31) << 2;      // 0..124
    }

    float acc[8][8];
#pragma unroll
    for (int i = 0; i < 8; i++)
#pragma unroll
        for (int j = 0; j < 8; j++) acc[i][j] = 0.f;

    const int nk = K >> 4;

    // --- load tile 0 into buffer 0 ---
#pragma unroll
    for (int u = 0; u < 2; u++) {
        float4 a4 = *(const float4*)(A + (size_t)(row0 + arr[u]) * K + acc_[u]);
        As[0][acc_[u] + 0][arr[u]] = a4.x;
        As[0][acc_[u] + 1][arr[u]] = a4.y;
        As[0][acc_[u] + 2][arr[u]] = a4.z;
        As[0][acc_[u] + 3][arr[u]] = a4.w;
        *(float4*)&Bs[0][brr[u]][bcc[u]] =
            *(const float4*)(Bm + (size_t)brr[u] * N + col0 + bcc[u]);
    }
    __syncthreads();

    for (int t = 0; t < nk; t++) {
        const int cur = t & 1;
        const int nxt = cur ^ 1;

        // prefetch next tile into registers (overlaps with compute below)
        float4 pa[2], pb[2];
        if (t + 1 < nk) {
            int k0n = (t + 1) << 4;
#pragma unroll
            for (int u = 0; u < 2; u++) {
                pa[u] = *(const float4*)(A + (size_t)(row0 + arr[u]) * K + k0n + acc_[u]);
                pb[u] = *(const float4*)(Bm + (size_t)(k0n + brr[u]) * N + col0 + bcc[u]);
            }
        }

        // compute on current buffer
#pragma unroll
        for (int kk = 0; kk < 16; kk++) {
            float a[8], bb[8];
            *(float4*)&a[0]  = *(float4*)&As[cur][kk][ty * 8];
            *(float4*)&a[4]  = *(float4*)&As[cur][kk][ty * 8 + 4];
            *(float4*)&bb[0] = *(float4*)&Bs[cur][kk][tx * 8];
            *(float4*)&bb[4] = *(float4*)&Bs[cur][kk][tx * 8 + 4];
#pragma unroll
            for (int i = 0; i < 8; i++)
#pragma unroll
                for (int j = 0; j < 8; j++)
                    acc[i][j] = fmaf(a[i], bb[j], acc[i][j]);
        }

        // commit prefetched tile to the other buffer
        if (t + 1 < nk) {
#pragma unroll
            for (int u = 0; u < 2; u++) {
                As[nxt][acc_[u] + 0][arr[u]] = pa[u].x;
                As[nxt][acc_[u] + 1][arr[u]] = pa[u].y;
                As[nxt][acc_[u] + 2][arr[u]] = pa[u].z;
                As[nxt][acc_[u] + 3][arr[u]] = pa[u].w;
                *(float4*)&Bs[nxt][brr[u]][bcc[u]] = pb[u];
            }
            __syncthreads();
        }
    }

    float bv[8];
#pragma unroll
    for (int j = 0; j < 8; j++) bv[j] = bias[col0 + tx * 8 + j];

#pragma unroll
    for (int i = 0; i < 8; i++) {
        float4 o0, o1;
        o0.x = acc[i][0] + bv[0]; o0.y = acc[i][1] + bv[1];
        o0.z = acc[i][2] + bv[2]; o0.w = acc[i][3] + bv[3];
        o1.x = acc[i][4] + bv[4]; o1.y = acc[i][5] + bv[5];
        o1.z = acc[i][6] + bv[6]; o1.w = acc[i][7] + bv[7];
        float* cp = C + (size_t)(row0 + ty * 8 + i) * N + col0 + tx * 8;
        *(float4*)cp       = o0;
        *(float4*)(cp + 4) = o1;
    }
}

// ---------------------------------------------------------------------------
// Latent projection: lat[b,h,s,l] = elu(proj[b,s,h*DH+ :] @ W + bias) + 1
// One CTA: 64 s-rows x one head. K=128, N=64.
// ---------------------------------------------------------------------------
__global__ void __launch_bounds__(256) latent_kernel(
    const float* __restrict__ P, const float* __restrict__ W,
    const float* __restrict__ bias, float* __restrict__ lat)
{
    extern __shared__ float sm[];
    float* It = sm;             // [128][68]  (d-major, transposed input tile)
    float* Ws = sm + 128 * 68;  // [128][68]  (d-major weights)

    const int tid = threadIdx.x;
    const int ty  = tid >> 4;
    const int tx  = tid & 15;
    const int s0  = blockIdx.x * 64;
    const int h   = blockIdx.y;
    const int b   = blockIdx.z;

    const float* ip = P + ((size_t)(b * Sc + s0)) * Ec + h * DHc;
#pragma unroll
    for (int u = 0; u < 8; u++) {
        int f  = tid + u * 256;     // 2048 float4s = 64 rows x 32 f4
        int r  = f >> 5;
        int c4 = (f & 31) << 2;
        float4 a4 = *(const float4*)(ip + (size_t)r * Ec + c4);
        It[(c4 + 0) * 68 + r] = a4.x;
        It[(c4 + 1) * 68 + r] = a4.y;
        It[(c4 + 2) * 68 + r] = a4.z;
        It[(c4 + 3) * 68 + r] = a4.w;
    }
    // W is [128][64] = 2048 float4s: d = f>>4 in 0..127, c4 = (f&15)<<2 in 0..60
#pragma unroll
    for (int u = 0; u < 8; u++) {
        int f  = tid + u * 256;     // 2048 float4s = 128 rows x 16 f4
        int d  = f >> 4;
        int c4 = (f & 15) << 2;
        *(float4*)&Ws[d * 68 + c4] = *(const float4*)(W + d * Lc + c4);
    }
    __syncthreads();

    float acc[4][4];
#pragma unroll
    for (int i = 0; i < 4; i++)
#pragma unroll
        for (int j = 0; j < 4; j++) acc[i][j] = 0.f;

    for (int d = 0; d < 128; d++) {
        float4 a4 = *(float4*)&It[d * 68 + ty * 4];
        float4 w4 = *(float4*)&Ws[d * 68 + tx * 4];
        float a[4] = {a4.x, a4.y, a4.z, a4.w};
        float w[4] = {w4.x, w4.y, w4.z, w4.w};
#pragma unroll
        for (int i = 0; i < 4; i++)
#pragma unroll
            for (int j = 0; j < 4; j++)
                acc[i][j] = fmaf(a[i], w[j], acc[i][j]);
    }

    float* op = lat + ((size_t)(b * Hc + h) * Sc + s0) * Lc;
#pragma unroll
    for (int i = 0; i < 4; i++) {
        int r = ty * 4 + i;
        float4 o;
        float v0 = acc[i][0] + bias[tx * 4 + 0];
        float v1 = acc[i][1] + bias[tx * 4 + 1];
        float v2 = acc[i][2] + bias[tx * 4 + 2];
        float v3 = acc[i][3] + bias[tx * 4 + 3];
        o.x = v0 > 0.f ? v0 + 1.f : __expf(v0);   // elu(x)+1
        o.y = v1 > 0.f ? v1 + 1.f : __expf(v1);
        o.z = v2 > 0.f ? v2 + 1.f : __expf(v2);
        o.w = v3 > 0.f ? v3 + 1.f : __expf(v3);
        *(float4*)(op + (size_t)r * Lc + tx * 4) = o;
    }
}

// ---------------------------------------------------------------------------
// Block attention. One CTA per (q-block=128 rows, head, batch).
// For each of 4 kv-blocks (512 keys): online softmax over 4 chunks of 128
// keys, finalize (divide by l) and += into gmem output.
// smem: Qt[64][132] Kt[64][132] Vs[128][132] Pt[128][132]  = 202752 B
// ---------------------------------------------------------------------------
__global__ void __launch_bounds__(256, 1) attn_kernel(
    const float* __restrict__ qlat, const float* __restrict__ klat,
    const float* __restrict__ v, float* __restrict__ att)
{
    extern __shared__ float sm[];
    float* Qt = sm;                  // 64 x 132 (l-major)
    float* Kt = Qt + 64 * 132;       // 64 x 132 (l-major)
    float* Vs = Kt + 64 * 132;       // 128 x 132 (key-major)
    float* Pt = Vs + 128 * 132;      // 128 x 132 (key-major, transposed P)

    const int tid = threadIdx.x;
    const int ty  = tid >> 4;
    const int tx  = tid & 15;
    const int r0  = ty * 8;
    const int c0  = tx * 8;
    const int qb  = blockIdx.x;
    const int h   = blockIdx.y;
    const int b   = blockIdx.z;

    // load Q tile (128 rows x 64), transposed into Qt[l][m]
    const float* qp = qlat + ((size_t)(b * Hc + h) * Sc + qb * 128) * Lc;
#pragma unroll
    for (int u = 0; u < 8; u++) {
        int f  = tid + u * 256;      // 2048 f4 = 128 rows x 16 f4
        int r  = f >> 4;
        int c4 = (f & 15) << 2;
        float4 a4 = *(const float4*)(qp + (size_t)r * Lc + c4);
        Qt[(c4 + 0) * 132 + r] = a4.x;
        Qt[(c4 + 1) * 132 + r] = a4.y;
        Qt[(c4 + 2) * 132 + r] = a4.z;
        Qt[(c4 + 3) * 132 + r] = a4.w;
    }

    float* ap = att + ((size_t)(b * Sc + qb * 128)) * Ec + h * DHc;

    for (int kvb = 0; kvb < 4; kvb++) {
        float o[8][8];
        float mrow[8], lrow[8];
#pragma unroll
        for (int i = 0; i < 8; i++) {
            mrow[i] = -1e30f;
            lrow[i] = 0.f;
#pragma unroll
            for (int j = 0; j < 8; j++) o[i][j] = 0.f;
        }

        for (int ch = 0; ch < 4; ch++) {
            __syncthreads();  // previous chunk's PV / Q load done before smem reuse
            // load K chunk (128 keys x 64) transposed into Kt[l][key]
            const float* kp = klat +
                ((size_t)(b * Hc + h) * Sc + kvb * 512 + ch * 128) * Lc;
#pragma unroll
            for (int u = 0; u < 8; u++) {
                int f  = tid + u * 256;
                int r  = f >> 4;
                int c4 = (f & 15) << 2;
                float4 a4 = *(const float4*)(kp + (size_t)r * Lc + c4);
                Kt[(c4 + 0) * 132 + r] = a4.x;
                Kt[(c4 + 1) * 132 + r] = a4.y;
                Kt[(c4 + 2) * 132 + r] = a4.z;
                Kt[(c4 + 3) * 132 + r] = a4.w;
            }
            // load V chunk (128 keys x 128 dims), row stride E
            const float* vp = v +
                ((size_t)(b * Sc + kvb * 512 + ch * 128)) * Ec + h * DHc;
#pragma unroll
            for (int u = 0; u < 16; u++) {
                int f  = tid + u * 256;   // 4096 f4 = 128 rows x 32 f4
                int r  = f >> 5;
                int c4 = (f & 31) << 2;
                *(float4*)&Vs[r * 132 + c4] =
                    *(const float4*)(vp + (size_t)r * Ec + c4);
            }
            __syncthreads();

            // S = Q @ K^T  (128x128, K-dim = L = 64)
            float sreg[8][8];
#pragma unroll
            for (int i = 0; i < 8; i++)
#pragma unroll
                for (int j = 0; j < 8; j++) sreg[i][j] = 0.f;

            for (int l = 0; l < 64; l++) {
                float a[8], bb[8];
                *(float4*)&a[0]  = *(float4*)&Qt[l * 132 + r0];
                *(float4*)&a[4]  = *(float4*)&Qt[l * 132 + r0 + 4];
                *(float4*)&bb[0] = *(float4*)&Kt[l * 132 + c0];
                *(float4*)&bb[4] = *(float4*)&Kt[l * 132 + c0 + 4];
#pragma unroll
                for (int i = 0; i < 8; i++)
#pragma unroll
                    for (int j = 0; j < 8; j++)
                        sreg[i][j] = fmaf(a[i], bb[j], sreg[i][j]);
            }

            // online softmax update (scale = 1/sqrt(64) = 0.125)
#pragma unroll
            for (int i = 0; i < 8; i++) {
                float cm = -1e30f;
#pragma unroll
                for (int j = 0; j < 8; j++) {
                    sreg[i][j] *= 0.125f;
                    cm = fmaxf(cm, sreg[i][j]);
                }
#pragma unroll
                for (int off = 8; off > 0; off >>= 1)
                    cm = fmaxf(cm, __shfl_xor_sync(0xffffffffu, cm, off));
                float mo   = mrow[i];
                float mn   = fmaxf(mo, cm);
                float corr = __expf(mo - mn);
                float ps   = 0.f;
#pragma unroll
                for (int j = 0; j < 8; j++) {
                    float p = __expf(sreg[i][j] - mn);
                    sreg[i][j] = p;
                    ps += p;
                }
#pragma unroll
                for (int off = 8; off > 0; off >>= 1)
                    ps += __shfl_xor_sync(0xffffffffu, ps, off);
                lrow[i] = lrow[i] * corr + ps;
                mrow[i] = mn;
#pragma unroll
                for (int j = 0; j < 8; j++) o[i][j] *= corr;
            }

            // stash P transposed: Pt[key][m]
#pragma unroll
            for (int j = 0; j < 8; j++)
#pragma unroll
                for (int i = 0; i < 8; i++)
                    Pt[(c0 + j) * 132 + r0 + i] = sreg[i][j];
            __syncthreads();

            // O += P @ V  (128x128, K-dim = 128 keys)
            for (int k = 0; k < 128; k++) {
                float a[8], bb[8];
                *(float4*)&a[0]  = *(float4*)&Pt[k * 132 + r0];
                *(float4*)&a[4]  = *(float4*)&Pt[k * 132 + r0 + 4];
                *(float4*)&bb[0] = *(float4*)&Vs[k * 132 + c0];
                *(float4*)&bb[4] = *(float4*)&Vs[k * 132 + c0 + 4];
#pragma unroll
                for (int i = 0; i < 8; i++)
#pragma unroll
                    for (int j = 0; j < 8; j++)
                        o[i][j] = fmaf(a[i], bb[j], o[i][j]);
            }
        }

        // finalize this kv block: att += O / l  (first block writes)
#pragma unroll
        for (int i = 0; i < 8; i++) {
            float inv = 1.f / lrow[i];
            float* orow = ap + (size_t)(r0 + i) * Ec + c0;
            float4 o0, o1;
            o0.x = o[i][0] * inv; o0.y = o[i][1] * inv;
            o0.z = o[i][2] * inv; o0.w = o[i][3] * inv;
            o1.x = o[i][4] * inv; o1.y = o[i][5] * inv;
            o1.z = o[i][6] * inv; o1.w = o[i][7] * inv;
            if (kvb) {
                float4 p0 = *(float4*)orow;
                float4 p1 = *(float4*)(orow + 4);
                o0.x += p0.x; o0.y += p0.y; o0.z += p0.z; o0.w += p0.w;
                o1.x += p1.x; o1.y += p1.y; o1.z += p1.z; o1.w += p1.w;
            }
            *(float4*)orow       = o0;
            *(float4*)(orow + 4) = o1;
        }
    }
}

// ---------------------------------------------------------------------------
// Per-head mixer: mix[r, h*DH + j] = gelu( att[r, h*DH + :] @ Wm + bm )
// One CTA: 64 rows x one head. K=128, N=128.
// ---------------------------------------------------------------------------
__global__ void __launch_bounds__(256) mixer_kernel(
    const float* __restrict__ att, const float* __restrict__ Wm,
    const float* __restrict__ bm, float* __restrict__ mix)
{
    extern __shared__ float sm[];
    float* At = sm;             // [128][68]  (d-major, transposed rows)
    float* Ws = sm + 128 * 68;  // [128][132] (d-major weights)

    const int tid = threadIdx.x;
    const int ty  = tid >> 4;
    const int tx  = tid & 15;
    const int r0g = blockIdx.x * 64;
    const int h   = blockIdx.y;

    const float* ip = att + (size_t)r0g * Ec + h * DHc;
#pragma unroll
    for (int u = 0; u < 8; u++) {
        int f  = tid + u * 256;     // 2048 f4 = 64 rows x 32 f4
        int r  = f >> 5;
        int c4 = (f & 31) << 2;
        float4 a4 = *(const float4*)(ip + (size_t)r * Ec + c4);
        At[(c4 + 0) * 68 + r] = a4.x;
        At[(c4 + 1) * 68 + r] = a4.y;
        At[(c4 + 2) * 68 + r] = a4.z;
        At[(c4 + 3) * 68 + r] = a4.w;
    }
#pragma unroll
    for (int u = 0; u < 16; u++) {
        int f  = tid + u * 256;     // 4096 f4 = 128 rows x 32 f4
        int d  = f >> 5;
        int c4 = (f & 31) << 2;
        *(float4*)&Ws[d * 132 + c4] = *(const float4*)(Wm + d * DHc + c4);
    }
    __syncthreads();

    float acc[4][8];
#pragma unroll
    for (int i = 0; i < 4; i++)
#pragma unroll
        for (int j = 0; j < 8; j++) acc[i][j] = 0.f;

    for (int d = 0; d < 128; d++) {
        float4 a4 = *(float4*)&At[d * 68 + ty * 4];
        float a[4] = {a4.x, a4.y, a4.z, a4.w};
        float w[8];
        *(float4*)&w[0] = *(float4*)&Ws[d * 132 + tx * 8];
        *(float4*)&w[4] = *(float4*)&Ws[d * 132 + tx * 8 + 4];
#pragma unroll
        for (int i = 0; i < 4; i++)
#pragma unroll
            for (int j = 0; j < 8; j++)
                acc[i][j] = fmaf(a[i], w[j], acc[i][j]);
    }

    float bvv[8];
#pragma unroll
    for (int j = 0; j < 8; j++) bvv[j] = bm[tx * 8 + j];

#pragma unroll
    for (int i = 0; i < 4; i++) {
        int r = r0g + ty * 4 + i;
        float ov[8];
#pragma unroll
        for (int j = 0; j < 8; j++) {
            float xg = acc[i][j] + bvv[j];
            // tanh-approx GELU (jax.nn.gelu default)
            float t = tanhf(0.7978845608028654f * (xg + 0.044715f * xg * xg * xg));
            ov[j] = 0.5f * xg * (1.f + t);
        }
        float* mp = mix + (size_t)r * Ec + h * DHc + tx * 8;
        *(float4*)mp       = *(float4*)&ov[0];
        *(float4*)(mp + 4) = *(float4*)&ov[4];
    }
}

// ---------------------------------------------------------------------------
// Launcher
// ---------------------------------------------------------------------------
extern "C" void kernel_launch(void* const* d_in, const int* in_sizes, int n_in,
                              void* d_out, int out_size)
{
    const float* x   = (const float*)d_in[0];
    const float* Wq  = (const float*)d_in[1];
    const float* bq  = (const float*)d_in[2];
    const float* Wk  = (const float*)d_in[3];
    const float* bk  = (const float*)d_in[4];
    const float* Wv  = (const float*)d_in[5];
    const float* bv  = (const float*)d_in[6];
    const float* Wo  = (const float*)d_in[7];
    const float* bo  = (const float*)d_in[8];
    const float* Wql = (const float*)d_in[9];
    const float* bql = (const float*)d_in[10];
    const float* Wkl = (const float*)d_in[11];
    const float* bkl = (const float*)d_in[12];
    const float* Wm  = (const float*)d_in[13];
    const float* bm  = (const float*)d_in[14];
    float* out = (float*)d_out;

    float *q, *k, *v, *ql, *kl, *att, *mix;
    cudaGetSymbolAddress((void**)&q,   g_q);
    cudaGetSymbolAddress((void**)&k,   g_k);
    cudaGetSymbolAddress((void**)&v,   g_v);
    cudaGetSymbolAddress((void**)&ql,  g_qlat);
    cudaGetSymbolAddress((void**)&kl,  g_klat);
    cudaGetSymbolAddress((void**)&att, g_att);
    cudaGetSymbolAddress((void**)&mix, g_mix);

    const int smem_lat  = (128 * 68 + 128 * 68) * 4;                 //  69632
    const int smem_attn = (64 * 132 * 2 + 128 * 132 * 2) * 4;        // 202752
    const int smem_mix  = (128 * 68 + 128 * 132) * 4;                // 102400
    cudaFuncSetAttribute(latent_kernel, cudaFuncAttributeMaxDynamicSharedMemorySize, smem_lat);
    cudaFuncSetAttribute(attn_kernel,   cudaFuncAttributeMaxDynamicSharedMemorySize, smem_attn);
    cudaFuncSetAttribute(mixer_kernel,  cudaFuncAttributeMaxDynamicSharedMemorySize, smem_mix);

    dim3 gg(Ec / 128, Mc / 128);   // (16, 32)

    gemm_bias_kernel<<<gg, 256>>>(x, Wq, bq, q, Mc, Ec, Ec);
    gemm_bias_kernel<<<gg, 256>>>(x, Wk, bk, k, Mc, Ec, Ec);
    gemm_bias_kernel<<<gg, 256>>>(x, Wv, bv, v, Mc, Ec, Ec);

    latent_kernel<<<dim3(Sc / 64, Hc, Bc), 256, smem_lat>>>(q, Wql, bql, ql);
    latent_kernel<<<dim3(Sc / 64, Hc, Bc), 256, smem_lat>>>(k, Wkl, bkl, kl);

    attn_kernel<<<dim3(Sc / 128, Hc, Bc), 256, smem_attn>>>(ql, kl, v, att);

    mixer_kernel<<<dim3(Mc / 64, Hc), 256, smem_mix>>>(att, Wm, bm, mix);

    gemm_bias_kernel<<<gg, 256>>>(mix, Wo, bo, out, Mc, Ec, Ec);
}

// round 8
// speedup vs baseline: 1.9123x; 1.9123x over previous
#include <cuda_runtime.h>
#include <math.h>
#include <stdint.h>

// ---------------------------------------------------------------------------
// Problem constants (fixed by the reference)
// ---------------------------------------------------------------------------
static constexpr int Bc  = 2;
static constexpr int Sc  = 2048;
static constexpr int Ec  = 2048;
static constexpr int Hc  = 16;
static constexpr int DHc = 128;
static constexpr int Lc  = 64;
static constexpr int Mc  = Bc * Sc;      // 4096 rows

// ---------------------------------------------------------------------------
// Device scratch
// ---------------------------------------------------------------------------
__device__ float g_q   [(size_t)Mc * Ec];
__device__ float g_k   [(size_t)Mc * Ec];
__device__ float g_v   [(size_t)Mc * Ec];
__device__ float g_qlat[(size_t)Bc * Hc * Sc * Lc];
__device__ float g_klat[(size_t)Bc * Hc * Sc * Lc];
__device__ float g_att [(size_t)Mc * Ec];
__device__ float g_mix [(size_t)Mc * Ec];

// ---------------------------------------------------------------------------
// tf32 tensor-core GEMM + bias : C[M,N] = A[M,K] @ B[K,N] + bias[N]
// 128x128 tile, BK=32, 256 threads (8 warps in 4x2), warp tile 32x64 via
// m16n8k8 tf32 mma.sync. cp.async double-buffered smem.
// A smem [128][36] (row-major, pad), B smem [32][136] (k-major, pad):
// both fragment-load patterns are bank-conflict-free permutations.
// ---------------------------------------------------------------------------
static constexpr int GT_ASTRIDE = 36;                 // floats per A row
static constexpr int GT_BSTRIDE = 136;                // floats per B k-row
static constexpr int GT_ABUF = 128 * GT_ASTRIDE;      // 4608 floats
static constexpr int GT_BBUF = 32  * GT_BSTRIDE;      // 4352 floats
static constexpr int GT_SMEM = 2 * (GT_ABUF + GT_BBUF) * 4;  // 71680 bytes

__device__ __forceinline__ uint32_t f2tf32(float x) {
    uint32_t r;
    asm("cvt.rna.tf32.f32 %0, %1;" : "=r"(r) : "f"(x));
    return r;
}

__device__ __forceinline__ void mma_tf32(float* d, const uint32_t* a, const uint32_t* b) {
    asm volatile(
        "mma.sync.aligned.m16n8k8.row.col.f32.tf32.tf32.f32 "
        "{%0,%1,%2,%3}, {%4,%5,%6,%7}, {%8,%9}, {%0,%1,%2,%3};"
        : "+f"(d[0]), "+f"(d[1]), "+f"(d[2]), "+f"(d[3])
        : "r"(a[0]), "r"(a[1]), "r"(a[2]), "r"(a[3]),
          "r"(b[0]), "r"(b[1]));
}

__global__ void __launch_bounds__(256) gemm_tf32_kernel(
    const float* __restrict__ A, const float* __restrict__ Bm,
    const float* __restrict__ bias, float* __restrict__ C,
    int M, int N, int K)
{
    extern __shared__ float sm[];
    float* As = sm;                  // [2][128][GT_ASTRIDE]
    float* Bs = sm + 2 * GT_ABUF;    // [2][32][GT_BSTRIDE]

    const int tid  = threadIdx.x;
    const int wid  = tid >> 5;       // 0..7
    const int lane = tid & 31;
    const int wm   = wid >> 1;       // warp row 0..3 -> rows wm*32
    const int wn   = wid & 1;        // warp col 0..1 -> cols wn*64
    const int g    = lane >> 2;      // 0..7
    const int t    = lane & 3;       // 0..3
    const int row0 = blockIdx.y * 128;
    const int col0 = blockIdx.x * 128;
    const int nk   = K >> 5;         // BK = 32

    float acc[2][8][4];
#pragma unroll
    for (int mi = 0; mi < 2; mi++)
#pragma unroll
        for (int nj = 0; nj < 8; nj++)
#pragma unroll
            for (int c = 0; c < 4; c++) acc[mi][nj][c] = 0.f;

    auto issue_tile = [&](int tt, int buf) {
        const int k0 = tt << 5;
        float* Ab = As + buf * GT_ABUF;
        float* Bb = Bs + buf * GT_BBUF;
#pragma unroll
        for (int u = 0; u < 4; u++) {            // A: 1024 float4
            int f   = tid + u * 256;
            int row = f >> 3;                    // 0..127
            int kc4 = (f & 7) << 2;              // 0..28
            uint32_t sa = (uint32_t)__cvta_generic_to_shared(
                Ab + row * GT_ASTRIDE + kc4);
            const float* ga = A + (size_t)(row0 + row) * K + k0 + kc4;
            asm volatile("cp.async.ca.shared.global [%0], [%1], 16;"
                         :: "r"(sa), "l"(ga));
        }
#pragma unroll
        for (int u = 0; u < 4; u++) {            // B: 1024 float4
            int f   = tid + u * 256;
            int kr  = f >> 5;                    // 0..31
            int nc4 = (f & 31) << 2;             // 0..124
            uint32_t sb = (uint32_t)__cvta_generic_to_shared(
                Bb + kr * GT_BSTRIDE + nc4);
            const float* gb = Bm + (size_t)(k0 + kr) * N + col0 + nc4;
            asm volatile("cp.async.ca.shared.global [%0], [%1], 16;"
                         :: "r"(sb), "l"(gb));
        }
        asm volatile("cp.async.commit_group;");
    };

    auto compute_tile = [&](int buf) {
        const float* Ab = As + buf * GT_ABUF;
        const float* Bb = Bs + buf * GT_BBUF;
#pragma unroll
        for (int k8 = 0; k8 < 4; k8++) {
            const int kb = k8 << 3;
            uint32_t af[2][4];
#pragma unroll
            for (int mi = 0; mi < 2; mi++) {
                const int m = wm * 32 + mi * 16;
                af[mi][0] = f2tf32(Ab[(m + g    ) * GT_ASTRIDE + kb + t    ]);
                af[mi][1] = f2tf32(Ab[(m + g + 8) * GT_ASTRIDE + kb + t    ]);
                af[mi][2] = f2tf32(Ab[(m + g    ) * GT_ASTRIDE + kb + t + 4]);
                af[mi][3] = f2tf32(Ab[(m + g + 8) * GT_ASTRIDE + kb + t + 4]);
            }
            uint32_t bf[8][2];
#pragma unroll
            for (int nj = 0; nj < 8; nj++) {
                const int n = wn * 64 + nj * 8;
                bf[nj][0] = f2tf32(Bb[(kb + t    ) * GT_BSTRIDE + n + g]);
                bf[nj][1] = f2tf32(Bb[(kb + t + 4) * GT_BSTRIDE + n + g]);
            }
#pragma unroll
            for (int mi = 0; mi < 2; mi++)
#pragma unroll
                for (int nj = 0; nj < 8; nj++)
                    mma_tf32(acc[mi][nj], af[mi], bf[nj]);
        }
    };

    issue_tile(0, 0);
    for (int tt = 0; tt < nk; tt++) {
        if (tt + 1 < nk) {
            issue_tile(tt + 1, (tt + 1) & 1);
            asm volatile("cp.async.wait_group 1;");
        } else {
            asm volatile("cp.async.wait_group 0;");
        }
        __syncthreads();
        compute_tile(tt & 1);
        __syncthreads();   // all reads of this buffer done before it is refilled
    }

    // epilogue: add bias, write fp32
#pragma unroll
    for (int mi = 0; mi < 2; mi++) {
#pragma unroll
        for (int nj = 0; nj < 8; nj++) {
            int r  = row0 + wm * 32 + mi * 16 + g;
            int cc = col0 + wn * 64 + nj * 8 + 2 * t;
            float b0 = bias[cc], b1 = bias[cc + 1];
            float2 v0 = make_float2(acc[mi][nj][0] + b0, acc[mi][nj][1] + b1);
            float2 v1 = make_float2(acc[mi][nj][2] + b0, acc[mi][nj][3] + b1);
            *(float2*)(C + (size_t)r       * N + cc) = v0;
            *(float2*)(C + (size_t)(r + 8) * N + cc) = v1;
        }
    }
}

// ---------------------------------------------------------------------------
// Latent projection: lat[b,h,s,l] = elu(proj[b,s,h*DH+ :] @ W + bias) + 1
// ---------------------------------------------------------------------------
__global__ void __launch_bounds__(256) latent_kernel(
    const float* __restrict__ P, const float* __restrict__ W,
    const float* __restrict__ bias, float* __restrict__ lat)
{
    extern __shared__ float sm[];
    float* It = sm;             // [128][68]
    float* Ws = sm + 128 * 68;  // [128][68]

    const int tid = threadIdx.x;
    const int ty  = tid >> 4;
    const int tx  = tid & 15;
    const int s0  = blockIdx.x * 64;
    const int h   = blockIdx.y;
    const int b   = blockIdx.z;

    const float* ip = P + ((size_t)(b * Sc + s0)) * Ec + h * DHc;
#pragma unroll
    for (int u = 0; u < 8; u++) {
        int f  = tid + u * 256;
        int r  = f >> 5;
        int c4 = (f & 31) << 2;
        float4 a4 = *(const float4*)(ip + (size_t)r * Ec + c4);
        It[(c4 + 0) * 68 + r] = a4.x;
        It[(c4 + 1) * 68 + r] = a4.y;
        It[(c4 + 2) * 68 + r] = a4.z;
        It[(c4 + 3) * 68 + r] = a4.w;
    }
#pragma unroll
    for (int u = 0; u < 8; u++) {
        int f  = tid + u * 256;     // 2048 float4s = 128 rows x 16 f4
        int d  = f >> 4;
        int c4 = (f & 15) << 2;
        *(float4*)&Ws[d * 68 + c4] = *(const float4*)(W + d * Lc + c4);
    }
    __syncthreads();

    float acc[4][4];
#pragma unroll
    for (int i = 0; i < 4; i++)
#pragma unroll
        for (int j = 0; j < 4; j++) acc[i][j] = 0.f;

    for (int d = 0; d < 128; d++) {
        float4 a4 = *(float4*)&It[d * 68 + ty * 4];
        float4 w4 = *(float4*)&Ws[d * 68 + tx * 4];
        float a[4] = {a4.x, a4.y, a4.z, a4.w};
        float w[4] = {w4.x, w4.y, w4.z, w4.w};
#pragma unroll
        for (int i = 0; i < 4; i++)
#pragma unroll
            for (int j = 0; j < 4; j++)
                acc[i][j] = fmaf(a[i], w[j], acc[i][j]);
    }

    float* op = lat + ((size_t)(b * Hc + h) * Sc + s0) * Lc;
#pragma unroll
    for (int i = 0; i < 4; i++) {
        int r = ty * 4 + i;
        float4 o;
        float v0 = acc[i][0] + bias[tx * 4 + 0];
        float v1 = acc[i][1] + bias[tx * 4 + 1];
        float v2 = acc[i][2] + bias[tx * 4 + 2];
        float v3 = acc[i][3] + bias[tx * 4 + 3];
        o.x = v0 > 0.f ? v0 + 1.f : __expf(v0);
        o.y = v1 > 0.f ? v1 + 1.f : __expf(v1);
        o.z = v2 > 0.f ? v2 + 1.f : __expf(v2);
        o.w = v3 > 0.f ? v3 + 1.f : __expf(v3);
        *(float4*)(op + (size_t)r * Lc + tx * 4) = o;
    }
}

// ---------------------------------------------------------------------------
// Block attention (unchanged from the passing R7 kernel)
// ---------------------------------------------------------------------------
__global__ void __launch_bounds__(256, 1) attn_kernel(
    const float* __restrict__ qlat, const float* __restrict__ klat,
    const float* __restrict__ v, float* __restrict__ att)
{
    extern __shared__ float sm[];
    float* Qt = sm;                  // 64 x 132
    float* Kt = Qt + 64 * 132;       // 64 x 132
    float* Vs = Kt + 64 * 132;       // 128 x 132
    float* Pt = Vs + 128 * 132;      // 128 x 132

    const int tid = threadIdx.x;
    const int ty  = tid >> 4;
    const int tx  = tid & 15;
    const int r0  = ty * 8;
    const int c0  = tx * 8;
    const int qb  = blockIdx.x;
    const int h   = blockIdx.y;
    const int b   = blockIdx.z;

    const float* qp = qlat + ((size_t)(b * Hc + h) * Sc + qb * 128) * Lc;
#pragma unroll
    for (int u = 0; u < 8; u++) {
        int f  = tid + u * 256;
        int r  = f >> 4;
        int c4 = (f & 15) << 2;
        float4 a4 = *(const float4*)(qp + (size_t)r * Lc + c4);
        Qt[(c4 + 0) * 132 + r] = a4.x;
        Qt[(c4 + 1) * 132 + r] = a4.y;
        Qt[(c4 + 2) * 132 + r] = a4.z;
        Qt[(c4 + 3) * 132 + r] = a4.w;
    }

    float* ap = att + ((size_t)(b * Sc + qb * 128)) * Ec + h * DHc;

    for (int kvb = 0; kvb < 4; kvb++) {
        float o[8][8];
        float mrow[8], lrow[8];
#pragma unroll
        for (int i = 0; i < 8; i++) {
            mrow[i] = -1e30f;
            lrow[i] = 0.f;
#pragma unroll
            for (int j = 0; j < 8; j++) o[i][j] = 0.f;
        }

        for (int ch = 0; ch < 4; ch++) {
            __syncthreads();
            const float* kp = klat +
                ((size_t)(b * Hc + h) * Sc + kvb * 512 + ch * 128) * Lc;
#pragma unroll
            for (int u = 0; u < 8; u++) {
                int f  = tid + u * 256;
                int r  = f >> 4;
                int c4 = (f & 15) << 2;
                float4 a4 = *(const float4*)(kp + (size_t)r * Lc + c4);
                Kt[(c4 + 0) * 132 + r] = a4.x;
                Kt[(c4 + 1) * 132 + r] = a4.y;
                Kt[(c4 + 2) * 132 + r] = a4.z;
                Kt[(c4 + 3) * 132 + r] = a4.w;
            }
            const float* vp = v +
                ((size_t)(b * Sc + kvb * 512 + ch * 128)) * Ec + h * DHc;
#pragma unroll
            for (int u = 0; u < 16; u++) {
                int f  = tid + u * 256;
                int r  = f >> 5;
                int c4 = (f & 31) << 2;
                *(float4*)&Vs[r * 132 + c4] =
                    *(const float4*)(vp + (size_t)r * Ec + c4);
            }
            __syncthreads();

            float sreg[8][8];
#pragma unroll
            for (int i = 0; i < 8; i++)
#pragma unroll
                for (int j = 0; j < 8; j++) sreg[i][j] = 0.f;

            for (int l = 0; l < 64; l++) {
                float a[8], bb[8];
                *(float4*)&a[0]  = *(float4*)&Qt[l * 132 + r0];
                *(float4*)&a[4]  = *(float4*)&Qt[l * 132 + r0 + 4];
                *(float4*)&bb[0] = *(float4*)&Kt[l * 132 + c0];
                *(float4*)&bb[4] = *(float4*)&Kt[l * 132 + c0 + 4];
#pragma unroll
                for (int i = 0; i < 8; i++)
#pragma unroll
                    for (int j = 0; j < 8; j++)
                        sreg[i][j] = fmaf(a[i], bb[j], sreg[i][j]);
            }

#pragma unroll
            for (int i = 0; i < 8; i++) {
                float cm = -1e30f;
#pragma unroll
                for (int j = 0; j < 8; j++) {
                    sreg[i][j] *= 0.125f;
                    cm = fmaxf(cm, sreg[i][j]);
                }
#pragma unroll
                for (int off = 8; off > 0; off >>= 1)
                    cm = fmaxf(cm, __shfl_xor_sync(0xffffffffu, cm, off));
                float mo   = mrow[i];
                float mn   = fmaxf(mo, cm);
                float corr = __expf(mo - mn);
                float ps   = 0.f;
#pragma unroll
                for (int j = 0; j < 8; j++) {
                    float p = __expf(sreg[i][j] - mn);
                    sreg[i][j] = p;
                    ps += p;
                }
#pragma unroll
                for (int off = 8; off > 0; off >>= 1)
                    ps += __shfl_xor_sync(0xffffffffu, ps, off);
                lrow[i] = lrow[i] * corr + ps;
                mrow[i] = mn;
#pragma unroll
                for (int j = 0; j < 8; j++) o[i][j] *= corr;
            }

#pragma unroll
            for (int j = 0; j < 8; j++)
#pragma unroll
                for (int i = 0; i < 8; i++)
                    Pt[(c0 + j) * 132 + r0 + i] = sreg[i][j];
            __syncthreads();

            for (int k = 0; k < 128; k++) {
                float a[8], bb[8];
                *(float4*)&a[0]  = *(float4*)&Pt[k * 132 + r0];
                *(float4*)&a[4]  = *(float4*)&Pt[k * 132 + r0 + 4];
                *(float4*)&bb[0] = *(float4*)&Vs[k * 132 + c0];
                *(float4*)&bb[4] = *(float4*)&Vs[k * 132 + c0 + 4];
#pragma unroll
                for (int i = 0; i < 8; i++)
#pragma unroll
                    for (int j = 0; j < 8; j++)
                        o[i][j] = fmaf(a[i], bb[j], o[i][j]);
            }
        }

#pragma unroll
        for (int i = 0; i < 8; i++) {
            float inv = 1.f / lrow[i];
            float* orow = ap + (size_t)(r0 + i) * Ec + c0;
            float4 o0, o1;
            o0.x = o[i][0] * inv; o0.y = o[i][1] * inv;
            o0.z = o[i][2] * inv; o0.w = o[i][3] * inv;
            o1.x = o[i][4] * inv; o1.y = o[i][5] * inv;
            o1.z = o[i][6] * inv; o1.w = o[i][7] * inv;
            if (kvb) {
                float4 p0 = *(float4*)orow;
                float4 p1 = *(float4*)(orow + 4);
                o0.x += p0.x; o0.y += p0.y; o0.z += p0.z; o0.w += p0.w;
                o1.x += p1.x; o1.y += p1.y; o1.z += p1.z; o1.w += p1.w;
            }
            *(float4*)orow       = o0;
            *(float4*)(orow + 4) = o1;
        }
    }
}

// ---------------------------------------------------------------------------
// Per-head mixer (unchanged)
// ---------------------------------------------------------------------------
__global__ void __launch_bounds__(256) mixer_kernel(
    const float* __restrict__ att, const float* __restrict__ Wm,
    const float* __restrict__ bm, float* __restrict__ mix)
{
    extern __shared__ float sm[];
    float* At = sm;             // [128][68]
    float* Ws = sm + 128 * 68;  // [128][132]

    const int tid = threadIdx.x;
    const int ty  = tid >> 4;
    const int tx  = tid & 15;
    const int r0g = blockIdx.x * 64;
    const int h   = blockIdx.y;

    const float* ip = att + (size_t)r0g * Ec + h * DHc;
#pragma unroll
    for (int u = 0; u < 8; u++) {
        int f  = tid + u * 256;
        int r  = f >> 5;
        int c4 = (f & 31) << 2;
        float4 a4 = *(const float4*)(ip + (size_t)r * Ec + c4);
        At[(c4 + 0) * 68 + r] = a4.x;
        At[(c4 + 1) * 68 + r] = a4.y;
        At[(c4 + 2) * 68 + r] = a4.z;
        At[(c4 + 3) * 68 + r] = a4.w;
    }
#pragma unroll
    for (int u = 0; u < 16; u++) {
        int f  = tid + u * 256;
        int d  = f >> 5;
        int c4 = (f & 31) << 2;
        *(float4*)&Ws[d * 132 + c4] = *(const float4*)(Wm + d * DHc + c4);
    }
    __syncthreads();

    float acc[4][8];
#pragma unroll
    for (int i = 0; i < 4; i++)
#pragma unroll
        for (int j = 0; j < 8; j++) acc[i][j] = 0.f;

    for (int d = 0; d < 128; d++) {
        float4 a4 = *(float4*)&At[d * 68 + ty * 4];
        float a[4] = {a4.x, a4.y, a4.z, a4.w};
        float w[8];
        *(float4*)&w[0] = *(float4*)&Ws[d * 132 + tx * 8];
        *(float4*)&w[4] = *(float4*)&Ws[d * 132 + tx * 8 + 4];
#pragma unroll
        for (int i = 0; i < 4; i++)
#pragma unroll
            for (int j = 0; j < 8; j++)
                acc[i][j] = fmaf(a[i], w[j], acc[i][j]);
    }

    float bvv[8];
#pragma unroll
    for (int j = 0; j < 8; j++) bvv[j] = bm[tx * 8 + j];

#pragma unroll
    for (int i = 0; i < 4; i++) {
        int r = r0g + ty * 4 + i;
        float ov[8];
#pragma unroll
        for (int j = 0; j < 8; j++) {
            float xg = acc[i][j] + bvv[j];
            float t = tanhf(0.7978845608028654f * (xg + 0.044715f * xg * xg * xg));
            ov[j] = 0.5f * xg * (1.f + t);
        }
        float* mp = mix + (size_t)r * Ec + h * DHc + tx * 8;
        *(float4*)mp       = *(float4*)&ov[0];
        *(float4*)(mp + 4) = *(float4*)&ov[4];
    }
}

// ---------------------------------------------------------------------------
// Launcher
// ---------------------------------------------------------------------------
extern "C" void kernel_launch(void* const* d_in, const int* in_sizes, int n_in,
                              void* d_out, int out_size)
{
    const float* x   = (const float*)d_in[0];
    const float* Wq  = (const float*)d_in[1];
    const float* bq  = (const float*)d_in[2];
    const float* Wk  = (const float*)d_in[3];
    const float* bk  = (const float*)d_in[4];
    const float* Wv  = (const float*)d_in[5];
    const float* bv  = (const float*)d_in[6];
    const float* Wo  = (const float*)d_in[7];
    const float* bo  = (const float*)d_in[8];
    const float* Wql = (const float*)d_in[9];
    const float* bql = (const float*)d_in[10];
    const float* Wkl = (const float*)d_in[11];
    const float* bkl = (const float*)d_in[12];
    const float* Wm  = (const float*)d_in[13];
    const float* bm  = (const float*)d_in[14];
    float* out = (float*)d_out;

    float *q, *k, *v, *ql, *kl, *att, *mix;
    cudaGetSymbolAddress((void**)&q,   g_q);
    cudaGetSymbolAddress((void**)&k,   g_k);
    cudaGetSymbolAddress((void**)&v,   g_v);
    cudaGetSymbolAddress((void**)&ql,  g_qlat);
    cudaGetSymbolAddress((void**)&kl,  g_klat);
    cudaGetSymbolAddress((void**)&att, g_att);
    cudaGetSymbolAddress((void**)&mix, g_mix);

    const int smem_lat  = (128 * 68 + 128 * 68) * 4;                 //  69632
    const int smem_attn = (64 * 132 * 2 + 128 * 132 * 2) * 4;        // 202752
    const int smem_mix  = (128 * 68 + 128 * 132) * 4;                // 102400
    cudaFuncSetAttribute(gemm_tf32_kernel, cudaFuncAttributeMaxDynamicSharedMemorySize, GT_SMEM);
    cudaFuncSetAttribute(latent_kernel, cudaFuncAttributeMaxDynamicSharedMemorySize, smem_lat);
    cudaFuncSetAttribute(attn_kernel,   cudaFuncAttributeMaxDynamicSharedMemorySize, smem_attn);
    cudaFuncSetAttribute(mixer_kernel,  cudaFuncAttributeMaxDynamicSharedMemorySize, smem_mix);

    dim3 gg(Ec / 128, Mc / 128);   // (16, 32)

    gemm_tf32_kernel<<<gg, 256, GT_SMEM>>>(x, Wq, bq, q, Mc, Ec, Ec);
    gemm_tf32_kernel<<<gg, 256, GT_SMEM>>>(x, Wk, bk, k, Mc, Ec, Ec);
    gemm_tf32_kernel<<<gg, 256, GT_SMEM>>>(x, Wv, bv, v, Mc, Ec, Ec);

    latent_kernel<<<dim3(Sc / 64, Hc, Bc), 256, smem_lat>>>(q, Wql, bql, ql);
    latent_kernel<<<dim3(Sc / 64, Hc, Bc), 256, smem_lat>>>(k, Wkl, bkl, kl);

    attn_kernel<<<dim3(Sc / 128, Hc, Bc), 256, smem_attn>>>(ql, kl, v, att);

    mixer_kernel<<<dim3(Mc / 64, Hc), 256, smem_mix>>>(att, Wm, bm, mix);

    gemm_tf32_kernel<<<gg, 256, GT_SMEM>>>(mix, Wo, bo, out, Mc, Ec, Ec);
}